// round 2
// baseline (speedup 1.0000x reference)
#include <cuda_runtime.h>
#include <cuda_bf16.h>
#include <math.h>

#define B_DIM 256
#define NB_DIM 50000
#define N_CYCLES 20000

// Scratch: angle matrix transposed to [NB, B] so the batch dim is contiguous.
__device__ float g_AT[(size_t)NB_DIM * B_DIM];   // 51.2 MB
__device__ int   g_off[N_CYCLES + 1];
__device__ double g_accum;

// ---------------------------------------------------------------------------
// Phase 1: A_T[i, b] = atan2f(s[b, i], c[b, i]); tiled transpose for
// coalesced reads AND writes. Also zeroes the accumulator.
// ---------------------------------------------------------------------------
__global__ void phase1_atan2_transpose(const float* __restrict__ c,
                                       const float* __restrict__ s) {
    __shared__ float tile[32][33];

    const int i0 = blockIdx.x * 32;   // branch index tile
    const int b0 = blockIdx.y * 32;   // batch index tile

    const int li = threadIdx.x;
    const int lb = threadIdx.y;

    const int i = i0 + li;
    const int b = b0 + lb;

    float a = 0.0f;
    if (i < NB_DIM) {
        const float cv = c[(size_t)b * NB_DIM + i];
        const float sv = s[(size_t)b * NB_DIM + i];
        a = atan2f(sv, cv);
    }
    tile[lb][li] = a;
    __syncthreads();

    // Transposed write: thread (x,y) writes A_T[i0+y, b0+x]
    const int ti = i0 + threadIdx.y;
    const int tb = b0 + threadIdx.x;   // always < 256
    if (ti < NB_DIM) {
        g_AT[(size_t)ti * B_DIM + tb] = tile[threadIdx.x][threadIdx.y];
    }

    if (blockIdx.x == 0 && blockIdx.y == 0 && threadIdx.x == 0 && threadIdx.y == 0) {
        g_accum = 0.0;
    }
}

// ---------------------------------------------------------------------------
// Offsets: g_off[r] = lower_bound(cyrows, r). 20001 independent binary
// searches, fully parallel (keeps the L2-latency chains off phase 2's
// critical path).
// ---------------------------------------------------------------------------
__global__ void build_offsets(const int* __restrict__ cyrows, int E) {
    const int r = blockIdx.x * blockDim.x + threadIdx.x;
    if (r > N_CYCLES) return;
    int lo = 0, hi = E;
    while (lo < hi) {
        const int m = (lo + hi) >> 1;
        if (__ldg(&cyrows[m]) < r) lo = m + 1; else hi = m;
    }
    g_off[r] = lo;
}

// ---------------------------------------------------------------------------
// Phase 2: one block per cycle, one thread per batch element.
// acc_b = sum over entries e in this row of sign[e] * A_T[ind[e], b].
// Then block-reduce sum(|acc_b|) and atomicAdd into the global accumulator.
// ---------------------------------------------------------------------------
__global__ __launch_bounds__(B_DIM) void phase2_cycle_sum(
    const float* __restrict__ cysigns,
    const int* __restrict__ cyinds) {

    const int r = blockIdx.x;
    const int start = g_off[r];
    const int end = g_off[r + 1];

    const int b = threadIdx.x;
    float acc = 0.0f;

    for (int e = start; e < end; ++e) {
        const float sg = __ldg(&cysigns[e]);
        const int idx = __ldg(&cyinds[e]);
        acc = fmaf(sg, __ldg(&g_AT[(size_t)idx * B_DIM + b]), acc);
    }

    float v = fabsf(acc);

    // Block reduction: warp shuffle, then cross-warp via smem.
    #pragma unroll
    for (int off = 16; off > 0; off >>= 1)
        v += __shfl_down_sync(0xFFFFFFFFu, v, off);

    __shared__ float warp_sums[8];
    const int lane = b & 31;
    const int wid = b >> 5;
    if (lane == 0) warp_sums[wid] = v;
    __syncthreads();

    if (wid == 0) {
        float w = (lane < 8) ? warp_sums[lane] : 0.0f;
        #pragma unroll
        for (int off = 4; off > 0; off >>= 1)
            w += __shfl_down_sync(0xFFFFFFFFu, w, off);
        if (lane == 0 && w != 0.0f)
            atomicAdd(&g_accum, (double)w);
    }
}

// ---------------------------------------------------------------------------
// Finalize: divide by the total element count of v_kvl and emit the scalar.
// ---------------------------------------------------------------------------
__global__ void finalize_out(float* __restrict__ out) {
    out[0] = (float)(g_accum * (1.0 / ((double)N_CYCLES * (double)B_DIM)));
}

extern "C" void kernel_launch(void* const* d_in, const int* in_sizes, int n_in,
                              void* d_out, int out_size) {
    const float* c       = (const float*)d_in[0];
    const float* s       = (const float*)d_in[1];
    const float* cysigns = (const float*)d_in[2];
    const int*   cyinds  = (const int*)d_in[3];
    const int*   cyrows  = (const int*)d_in[4];
    float* out = (float*)d_out;
    const int E = in_sizes[4];

    // Phase 1: 32x32 tiles over [B=256, NB=50000]
    dim3 t1(32, 32);
    dim3 g1((NB_DIM + 31) / 32, B_DIM / 32);
    phase1_atan2_transpose<<<g1, t1>>>(c, s);

    // Offsets: 20001 binary searches
    build_offsets<<<(N_CYCLES + 1 + 255) / 256, 256>>>(cyrows, E);

    // Phase 2: one block per cycle
    phase2_cycle_sum<<<N_CYCLES, B_DIM>>>(cysigns, cyinds);

    // Finalize
    finalize_out<<<1, 1>>>(out);
}

// round 3
// speedup vs baseline: 1.2844x; 1.2844x over previous
#include <cuda_runtime.h>
#include <cuda_fp16.h>
#include <math.h>

#define B_DIM    256
#define B_HALF2  (B_DIM / 2)
#define NB_DIM   50000
#define N_CYC    20000
#define G_CYC    8            // cycles per phase-2 block
#define P2_THREADS 128        // each thread handles 2 batches via half2
#define P2_GRID  (N_CYC / G_CYC)
#define TILE     256          // entries prefetched per smem tile

// Angle matrix transposed to [NB, B], fp16: batch contiguous -> coalesced gathers.
__device__ __half2  g_AT[(size_t)NB_DIM * B_HALF2];   // 25.6 MB
__device__ int      g_off[N_CYC + 1];
__device__ double   g_accum;
__device__ unsigned g_done;

// ---------------------------------------------------------------------------
// Branchless fast atan2: Hastings minimax on [0,1], |err| < 1e-5 rad.
// (Error is subdominant to the fp16 storage quantization of ~5e-4.)
// ---------------------------------------------------------------------------
__device__ __forceinline__ float fast_atan2f(float y, float x) {
    const float ax = fabsf(x), ay = fabsf(y);
    const float mx = fmaxf(ax, ay), mn = fminf(ax, ay);
    const float t = __fdividef(mn, mx);
    const float a = t * t;
    float r = fmaf(a, 0.0208351f, -0.0851330f);
    r = fmaf(r, a, 0.1801410f);
    r = fmaf(r, a, -0.3302995f);
    r = fmaf(r, a, 0.9998660f);
    r = r * t;
    if (ay > ax)  r = 1.57079632679f - r;
    if (x < 0.0f) r = 3.14159265359f - r;
    return copysignf(r, y);
}

// ---------------------------------------------------------------------------
// Phase 1: A_T[i, b] = (half)atan2(s[b,i], c[b,i]); 32x32 smem transpose so
// reads AND writes are coalesced.
// ---------------------------------------------------------------------------
__global__ void phase1_atan2_transpose(const float* __restrict__ c,
                                       const float* __restrict__ s) {
    __shared__ float tile[32][33];

    const int i0 = blockIdx.x * 32;
    const int b0 = blockIdx.y * 32;
    const int i = i0 + threadIdx.x;
    const int b = b0 + threadIdx.y;

    float a = 0.0f;
    if (i < NB_DIM) {
        const float cv = c[(size_t)b * NB_DIM + i];
        const float sv = s[(size_t)b * NB_DIM + i];
        a = fast_atan2f(sv, cv);
    }
    tile[threadIdx.y][threadIdx.x] = a;
    __syncthreads();

    const int ti = i0 + threadIdx.y;
    const int tb = b0 + threadIdx.x;
    if (ti < NB_DIM) {
        ((__half*)g_AT)[(size_t)ti * B_DIM + tb] =
            __float2half_rn(tile[threadIdx.x][threadIdx.y]);
    }
}

// ---------------------------------------------------------------------------
// Offsets: g_off[r] = lower_bound(cyrows, r); also resets the accumulators
// for this graph replay (runs before phase 2 in-stream).
// ---------------------------------------------------------------------------
__global__ void build_offsets(const int* __restrict__ cyrows, int E) {
    const int r = blockIdx.x * blockDim.x + threadIdx.x;
    if (r > N_CYC) return;
    if (r == 0) { g_accum = 0.0; g_done = 0u; }
    int lo = 0, hi = E;
    while (lo < hi) {
        const int m = (lo + hi) >> 1;
        if (__ldg(&cyrows[m]) < r) lo = m + 1; else hi = m;
    }
    g_off[r] = lo;
}

// ---------------------------------------------------------------------------
// Phase 2: block = G_CYC cycles; prefetch entry metadata into smem so the
// inner loop's gathers are independent back-to-back LDGs (no latency chain).
// Thread t accumulates batches 2t and 2t+1 (half2 loads). Segment boundaries
// detected from smem row ids. Last block writes the final scalar.
// ---------------------------------------------------------------------------
__global__ __launch_bounds__(P2_THREADS) void phase2_cycle_sum(
    const float* __restrict__ cysigns,
    const int*   __restrict__ cyinds,
    const int*   __restrict__ cyrows,
    float*       __restrict__ out) {

    __shared__ int   sh_idx[TILE];
    __shared__ float sh_sg[TILE];
    __shared__ int   sh_row[TILE];
    __shared__ float warp_sums[P2_THREADS / 32];

    const int tid = threadIdx.x;
    const int r0 = blockIdx.x * G_CYC;
    const int start = g_off[r0];
    const int end   = g_off[r0 + G_CYC];

    float acc0 = 0.0f, acc1 = 0.0f, sum = 0.0f;
    int cur_row = -1;

    for (int base = start; base < end; base += TILE) {
        const int n = min(TILE, end - base);
        __syncthreads();
        for (int j = tid; j < n; j += P2_THREADS) {
            sh_idx[j] = __ldg(&cyinds[base + j]) * B_HALF2;
            sh_sg[j]  = __ldg(&cysigns[base + j]);
            sh_row[j] = __ldg(&cyrows[base + j]);
        }
        __syncthreads();

        #pragma unroll 4
        for (int e = 0; e < n; ++e) {
            const int r = sh_row[e];
            if (r != cur_row) {                 // uniform across block
                sum += fabsf(acc0) + fabsf(acc1);
                acc0 = 0.0f; acc1 = 0.0f;
                cur_row = r;
            }
            const float sg = sh_sg[e];
            const float2 v = __half22float2(g_AT[(size_t)sh_idx[e] + tid]);
            acc0 = fmaf(sg, v.x, acc0);
            acc1 = fmaf(sg, v.y, acc1);
        }
    }
    sum += fabsf(acc0) + fabsf(acc1);

    // Block reduction
    #pragma unroll
    for (int off = 16; off > 0; off >>= 1)
        sum += __shfl_down_sync(0xFFFFFFFFu, sum, off);
    const int lane = tid & 31, wid = tid >> 5;
    if (lane == 0) warp_sums[wid] = sum;
    __syncthreads();
    if (wid == 0) {
        float w = (lane < P2_THREADS / 32) ? warp_sums[lane] : 0.0f;
        #pragma unroll
        for (int off = 2; off > 0; off >>= 1)
            w += __shfl_down_sync(0xFFFFFFFFu, w, off);
        if (lane == 0) {
            if (w != 0.0f) atomicAdd(&g_accum, (double)w);
            __threadfence();
            const unsigned ticket = atomicAdd(&g_done, 1u);
            if (ticket == (unsigned)(gridDim.x - 1)) {
                __threadfence();
                const double total = *((volatile double*)&g_accum);
                out[0] = (float)(total * (1.0 / ((double)N_CYC * (double)B_DIM)));
            }
        }
    }
}

extern "C" void kernel_launch(void* const* d_in, const int* in_sizes, int n_in,
                              void* d_out, int out_size) {
    const float* c       = (const float*)d_in[0];
    const float* s       = (const float*)d_in[1];
    const float* cysigns = (const float*)d_in[2];
    const int*   cyinds  = (const int*)d_in[3];
    const int*   cyrows  = (const int*)d_in[4];
    float* out = (float*)d_out;
    const int E = in_sizes[4];

    dim3 t1(32, 32);
    dim3 g1((NB_DIM + 31) / 32, B_DIM / 32);
    phase1_atan2_transpose<<<g1, t1>>>(c, s);

    build_offsets<<<(N_CYC + 1 + 255) / 256, 256>>>(cyrows, E);

    phase2_cycle_sum<<<P2_GRID, P2_THREADS>>>(cysigns, cyinds, cyrows, out);
}

// round 5
// speedup vs baseline: 2.1667x; 1.6870x over previous
#include <cuda_runtime.h>
#include <cuda_fp16.h>
#include <math.h>

#define B_DIM     256
#define B_HALF2   (B_DIM / 2)      // 128 half2 per A_T row
#define NB_DIM    50000
#define N_CYC     20000
#define G_CYC     8                // cycles per phase-2 block
#define P2_THREADS 128
#define P2_GRID   (N_CYC / G_CYC)
#define P2_TILE   128              // entries staged per smem tile

// A_T[i][bp] as packed half2 (batches 2bp, 2bp+1), batch-contiguous rows.
__device__ unsigned g_ATu[(size_t)NB_DIM * B_HALF2];   // 25.6 MB
__device__ int      g_off[N_CYC + 1];
__device__ double   g_accum;
__device__ unsigned g_done;

// ---------------------------------------------------------------------------
// Branchless fast atan2 (minimax, |err| < 1e-5 rad; subdominant to fp16
// storage quantization).
// ---------------------------------------------------------------------------
__device__ __forceinline__ float fast_atan2f(float y, float x) {
    const float ax = fabsf(x), ay = fabsf(y);
    const float mx = fmaxf(ax, ay), mn = fminf(ax, ay);
    const float t = __fdividef(mn, mx);
    const float a = t * t;
    float r = fmaf(a, 0.0208351f, -0.0851330f);
    r = fmaf(r, a, 0.1801410f);
    r = fmaf(r, a, -0.3302995f);
    r = fmaf(r, a, 0.9998660f);
    r = r * t;
    if (ay > ax)  r = 1.57079632679f - r;
    if (x < 0.0f) r = 3.14159265359f - r;
    return copysignf(r, y);
}

// ---------------------------------------------------------------------------
// Phase 1: A_T[i][b] = (half)atan2(s[b,i], c[b,i]).
// Tile = 64 i x 64 b per block of (16,32) threads; thread handles a batch
// PAIR (b1, b1+1) x 4 consecutive i via float4 loads (4x LDG.128, 8 atan2),
// packs each i into half2(b1, b1+1), transposes via smem at uint granularity,
// writes coalesced 128B rows.
// ---------------------------------------------------------------------------
__global__ void phase1_atan2_transpose(const float* __restrict__ c,
                                       const float* __restrict__ s) {
    __shared__ unsigned tile[64][33];   // [i_local][b_pair]

    const int tx = threadIdx.x;         // 0..15 : i-quad
    const int ty = threadIdx.y;         // 0..31 : b-pair
    const int i_base = blockIdx.x * 64;
    const int b_base = blockIdx.y * 64;

    const int i0 = i_base + tx * 4;
    const int b1 = b_base + 2 * ty;
    const int b2 = b1 + 1;

    if (i0 < NB_DIM) {   // NB_DIM % 4 == 0, so float4 is fully in-bounds
        const float4 c1 = *(const float4*)(c + (size_t)b1 * NB_DIM + i0);
        const float4 s1 = *(const float4*)(s + (size_t)b1 * NB_DIM + i0);
        const float4 c2 = *(const float4*)(c + (size_t)b2 * NB_DIM + i0);
        const float4 s2 = *(const float4*)(s + (size_t)b2 * NB_DIM + i0);

        __half2 h0 = __floats2half2_rn(fast_atan2f(s1.x, c1.x), fast_atan2f(s2.x, c2.x));
        __half2 h1 = __floats2half2_rn(fast_atan2f(s1.y, c1.y), fast_atan2f(s2.y, c2.y));
        __half2 h2 = __floats2half2_rn(fast_atan2f(s1.z, c1.z), fast_atan2f(s2.z, c2.z));
        __half2 h3 = __floats2half2_rn(fast_atan2f(s1.w, c1.w), fast_atan2f(s2.w, c2.w));

        tile[tx * 4 + 0][ty] = *reinterpret_cast<unsigned*>(&h0);
        tile[tx * 4 + 1][ty] = *reinterpret_cast<unsigned*>(&h1);
        tile[tx * 4 + 2][ty] = *reinterpret_cast<unsigned*>(&h2);
        tile[tx * 4 + 3][ty] = *reinterpret_cast<unsigned*>(&h3);
    }
    __syncthreads();

    // Output: 64 rows (i) x 32 uints (b-pairs). 16 warps -> 4 rows each.
    const int tid  = ty * 16 + tx;
    const int w    = tid >> 5;          // 0..15
    const int lane = tid & 31;
    #pragma unroll
    for (int k = 0; k < 4; ++k) {
        const int r  = w + 16 * k;      // i_local
        const int gi = i_base + r;
        if (gi < NB_DIM)
            g_ATu[(size_t)gi * B_HALF2 + (b_base >> 1) + lane] = tile[r][lane];
    }
}

// ---------------------------------------------------------------------------
// Offsets: g_off[r] = lower_bound(cyrows, r); also resets accumulators for
// this graph replay.
// ---------------------------------------------------------------------------
__global__ void build_offsets(const int* __restrict__ cyrows, int E) {
    const int r = blockIdx.x * blockDim.x + threadIdx.x;
    if (r > N_CYC) return;
    if (r == 0) { g_accum = 0.0; g_done = 0u; }
    int lo = 0, hi = E;
    while (lo < hi) {
        const int m = (lo + hi) >> 1;
        if (__ldg(&cyrows[m]) < r) lo = m + 1; else hi = m;
    }
    g_off[r] = lo;
}

// ---------------------------------------------------------------------------
// Phase 2: block = G_CYC cycles. Staging packs, per entry:
//   .x = idx*B_HALF2 | (row_change ? 1<<31 : 0)
//   .y = sign<0 ? 0x80008000 : 0     (XOR mask applies the sign to half2)
// Inner loop: LDS.64 + LDG.32 + XOR + HADD2; flush |.| to f32 on row change.
// Last block writes the final scalar.
// ---------------------------------------------------------------------------
__global__ __launch_bounds__(P2_THREADS) void phase2_cycle_sum(
    const float* __restrict__ cysigns,
    const int*   __restrict__ cyinds,
    const int*   __restrict__ cyrows,
    float*       __restrict__ out) {

    __shared__ uint2 sh[P2_TILE];
    __shared__ float warp_sums[P2_THREADS / 32];

    const int tid = threadIdx.x;
    const int r0 = blockIdx.x * G_CYC;
    const int start = g_off[r0];
    const int end   = g_off[r0 + G_CYC];

    __half2 acc = __half2half2(__ushort_as_half(0));
    float sum = 0.0f;

    for (int base = start; base < end; base += P2_TILE) {
        const int n = min(P2_TILE, end - base);
        __syncthreads();
        for (int j = tid; j < n; j += P2_THREADS) {
            const int e = base + j;
            const int idx = __ldg(&cyinds[e]);
            unsigned m = __float_as_uint(__ldg(&cysigns[e])) & 0x80000000u;
            m |= m >> 16;
            const int row = __ldg(&cyrows[e]);
            const int prev = (e > start) ? __ldg(&cyrows[e - 1]) : -1;
            const unsigned flag = (row != prev) ? 0x80000000u : 0u;
            sh[j] = make_uint2((unsigned)(idx * B_HALF2) | flag, m);
        }
        __syncthreads();

        #pragma unroll 4
        for (int e = 0; e < n; ++e) {
            const uint2 p = sh[e];
            if (p.x & 0x80000000u) {          // uniform across block
                const float2 f = __half22float2(acc);
                sum += fabsf(f.x) + fabsf(f.y);
                acc = __half2half2(__ushort_as_half(0));
            }
            unsigned u = g_ATu[(size_t)(p.x & 0x7FFFFFFFu) + tid];
            u ^= p.y;
            acc = __hadd2(acc, *reinterpret_cast<__half2*>(&u));
        }
    }
    {
        const float2 f = __half22float2(acc);
        sum += fabsf(f.x) + fabsf(f.y);
    }

    // Block reduction
    #pragma unroll
    for (int off = 16; off > 0; off >>= 1)
        sum += __shfl_down_sync(0xFFFFFFFFu, sum, off);
    const int lane = tid & 31, wid = tid >> 5;
    if (lane == 0) warp_sums[wid] = sum;
    __syncthreads();
    if (wid == 0) {
        float w = (lane < P2_THREADS / 32) ? warp_sums[lane] : 0.0f;
        #pragma unroll
        for (int off = 2; off > 0; off >>= 1)
            w += __shfl_down_sync(0xFFFFFFFFu, w, off);
        if (lane == 0) {
            if (w != 0.0f) atomicAdd(&g_accum, (double)w);
            __threadfence();
            const unsigned ticket = atomicAdd(&g_done, 1u);
            if (ticket == (unsigned)(gridDim.x - 1)) {
                __threadfence();
                const double total = *((volatile double*)&g_accum);
                out[0] = (float)(total * (1.0 / ((double)N_CYC * (double)B_DIM)));
            }
        }
    }
}

extern "C" void kernel_launch(void* const* d_in, const int* in_sizes, int n_in,
                              void* d_out, int out_size) {
    const float* c       = (const float*)d_in[0];
    const float* s       = (const float*)d_in[1];
    const float* cysigns = (const float*)d_in[2];
    const int*   cyinds  = (const int*)d_in[3];
    const int*   cyrows  = (const int*)d_in[4];
    float* out = (float*)d_out;
    const int E = in_sizes[4];

    dim3 t1(16, 32);
    dim3 g1((NB_DIM + 63) / 64, B_DIM / 64);
    phase1_atan2_transpose<<<g1, t1>>>(c, s);

    build_offsets<<<(N_CYC + 1 + 255) / 256, 256>>>(cyrows, E);

    phase2_cycle_sum<<<P2_GRID, P2_THREADS>>>(cysigns, cyinds, cyrows, out);
}

// round 7
// speedup vs baseline: 2.9309x; 1.3527x over previous
#include <cuda_runtime.h>
#include <cuda_fp16.h>
#include <math.h>

#define B_DIM      256
#define B_HALF2    (B_DIM / 2)       // 128 half2 = 64 uint2 per A_T row
#define B_UINT2    64
#define NB_DIM     50000
#define N_CYC      20000
#define P2_THREADS 64
#define P2_BASE    64                // entries owned per phase-2 block (nominal)
#define P2_EXT     160               // staged entries (64 + 96 slack)

// A_T[i] = 256 batch angles as fp16, row = 64 uint2 = 512 B.
__device__ uint2    g_AT2[(size_t)NB_DIM * B_UINT2];   // 25.6 MB
__device__ double   g_accum;
__device__ unsigned g_done;

// ---------------------------------------------------------------------------
// Branchless fast atan2 (minimax, |err| < 1e-5 rad; subdominant to fp16
// storage quantization).
// ---------------------------------------------------------------------------
__device__ __forceinline__ float fast_atan2f(float y, float x) {
    const float ax = fabsf(x), ay = fabsf(y);
    const float mx = fmaxf(ax, ay), mn = fminf(ax, ay);
    const float t = __fdividef(mn, mx);
    const float a = t * t;
    float r = fmaf(a, 0.0208351f, -0.0851330f);
    r = fmaf(r, a, 0.1801410f);
    r = fmaf(r, a, -0.3302995f);
    r = fmaf(r, a, 0.9998660f);
    r = r * t;
    if (ay > ax)  r = 1.57079632679f - r;
    if (x < 0.0f) r = 3.14159265359f - r;
    return copysignf(r, y);
}

__device__ __forceinline__ unsigned pack_pair(float a, float b) {
    __half2 h = __floats2half2_rn(a, b);
    return *reinterpret_cast<unsigned*>(&h);
}

// ---------------------------------------------------------------------------
// Phase 1: A_T[i][b] = (half)atan2(s[b,i], c[b,i]).
// Tile 64 i x 64 b, block (16,16): thread handles i-quad x TWO batch-pairs
// (8x LDG.128 front-batched, 16 atan2). c/s loaded streaming (__ldcs) so
// they don't evict A_T from L2. Transpose via smem, coalesced 128B rows out.
// ---------------------------------------------------------------------------
__global__ void phase1_atan2_transpose(const float* __restrict__ c,
                                       const float* __restrict__ s) {
    __shared__ unsigned tile[64][33];

    const int tx = threadIdx.x;          // 0..15 : i-quad
    const int ty = threadIdx.y;          // 0..15 : base b-pair
    const int i_base = blockIdx.x * 64;
    const int b_base = blockIdx.y * 64;
    const int i0 = i_base + tx * 4;

    if (i0 < NB_DIM) {                   // i0%4==0, NB_DIM%4==0 -> safe float4
        const int bA = b_base + 2 * ty;          // pair A: batches bA, bA+1
        const int bB = b_base + 2 * (ty + 16);   // pair B

        const float4* cp = (const float4*)(c + i0);
        const float4* sp = (const float4*)(s + i0);
        const size_t q = (size_t)NB_DIM / 4;

        // Front-batch all 8 loads for MLP.
        const float4 cA1 = __ldcs(cp + (size_t)bA * q);
        const float4 sA1 = __ldcs(sp + (size_t)bA * q);
        const float4 cA2 = __ldcs(cp + (size_t)(bA + 1) * q);
        const float4 sA2 = __ldcs(sp + (size_t)(bA + 1) * q);
        const float4 cB1 = __ldcs(cp + (size_t)bB * q);
        const float4 sB1 = __ldcs(sp + (size_t)bB * q);
        const float4 cB2 = __ldcs(cp + (size_t)(bB + 1) * q);
        const float4 sB2 = __ldcs(sp + (size_t)(bB + 1) * q);

        tile[tx*4+0][ty]    = pack_pair(fast_atan2f(sA1.x, cA1.x), fast_atan2f(sA2.x, cA2.x));
        tile[tx*4+1][ty]    = pack_pair(fast_atan2f(sA1.y, cA1.y), fast_atan2f(sA2.y, cA2.y));
        tile[tx*4+2][ty]    = pack_pair(fast_atan2f(sA1.z, cA1.z), fast_atan2f(sA2.z, cA2.z));
        tile[tx*4+3][ty]    = pack_pair(fast_atan2f(sA1.w, cA1.w), fast_atan2f(sA2.w, cA2.w));
        tile[tx*4+0][ty+16] = pack_pair(fast_atan2f(sB1.x, cB1.x), fast_atan2f(sB2.x, cB2.x));
        tile[tx*4+1][ty+16] = pack_pair(fast_atan2f(sB1.y, cB1.y), fast_atan2f(sB2.y, cB2.y));
        tile[tx*4+2][ty+16] = pack_pair(fast_atan2f(sB1.z, cB1.z), fast_atan2f(sB2.z, cB2.z));
        tile[tx*4+3][ty+16] = pack_pair(fast_atan2f(sB1.w, cB1.w), fast_atan2f(sB2.w, cB2.w));
    }
    __syncthreads();

    // 8 warps x 8 rows: coalesced 32-uint (128B) row writes.
    const int tid  = ty * 16 + tx;
    const int w    = tid >> 5;
    const int lane = tid & 31;
    unsigned* ATu = (unsigned*)g_AT2;
    #pragma unroll
    for (int k = 0; k < 8; ++k) {
        const int r  = w + 8 * k;
        const int gi = i_base + r;
        if (gi < NB_DIM)
            ATu[(size_t)gi * B_HALF2 + (b_base >> 1) + lane] = tile[r][lane];
    }

    if (blockIdx.x == 0 && blockIdx.y == 0 && tid == 0) {
        g_accum = 0.0;
        g_done = 0u;
    }
}

// ---------------------------------------------------------------------------
// Phase 2: entry-partitioned (64 entries/block). Block stages up to 160
// entries with row-change flags, owns the rows STARTING in its 64-entry
// span, processes them with LDG.64 gathers; sign applied as XOR mask,
// accumulation in half2, |.| flushed to f32 at row changes.
// Last block writes the final scalar.
// ---------------------------------------------------------------------------
__global__ __launch_bounds__(P2_THREADS) void phase2_cycle_sum(
    const float* __restrict__ cysigns,
    const int*   __restrict__ cyinds,
    const int*   __restrict__ cyrows,
    float*       __restrict__ out,
    int E) {

    __shared__ uint2 sh[P2_EXT];
    __shared__ int   sh_se[2];
    __shared__ float warp_sums[2];

    const int tid  = threadIdx.x;
    const int base = blockIdx.x * P2_BASE;
    const int n    = min(P2_EXT, E - base);

    // Stage: .x = idx*64 | rowchange<<31, .y = sign xor-mask for half2.
    for (int j = tid; j < n; j += P2_THREADS) {
        const int e = base + j;
        const int idx = __ldg(&cyinds[e]);
        unsigned m = __float_as_uint(__ldg(&cysigns[e])) & 0x80000000u;
        m |= m >> 16;
        const int row  = __ldg(&cyrows[e]);
        const int prev = (e > 0) ? __ldg(&cyrows[e - 1]) : -1;
        const unsigned flag = (row != prev) ? 0x80000000u : 0u;
        sh[j] = make_uint2((unsigned)(idx * B_UINT2) | flag, m);
    }
    __syncthreads();

    if (tid == 0) {
        int st = 0;
        while (st < n && !(sh[st].x & 0x80000000u)) ++st;
        int en = (P2_BASE < n) ? P2_BASE : n;
        while (en < n && !(sh[en].x & 0x80000000u)) ++en;
        sh_se[0] = st;
        sh_se[1] = en;
    }
    __syncthreads();
    const int st = sh_se[0];
    const int en = sh_se[1];

    const __half2 h2z = __half2half2(__ushort_as_half(0));
    __half2 acc0 = h2z, acc1 = h2z;
    float sum = 0.0f;

    #pragma unroll 4
    for (int j = st; j < en; ++j) {
        const uint2 p = sh[j];
        if (p.x & 0x80000000u) {             // uniform across block
            const float2 f0 = __half22float2(acc0);
            const float2 f1 = __half22float2(acc1);
            sum += fabsf(f0.x) + fabsf(f0.y) + fabsf(f1.x) + fabsf(f1.y);
            acc0 = h2z; acc1 = h2z;
        }
        uint2 u = g_AT2[(size_t)(p.x & 0x7FFFFFFFu) + tid];
        u.x ^= p.y;
        u.y ^= p.y;
        acc0 = __hadd2(acc0, *reinterpret_cast<__half2*>(&u.x));
        acc1 = __hadd2(acc1, *reinterpret_cast<__half2*>(&u.y));
    }

    // Fallback (statistically never taken): the block's last row extends
    // beyond the staged window -> finish it straight from global memory.
    if (en == n && st < en && base + n < E) {
        const int row = __ldg(&cyrows[base + n - 1]);
        for (int e = base + n; e < E && __ldg(&cyrows[e]) == row; ++e) {
            const int idx = __ldg(&cyinds[e]);
            unsigned m = __float_as_uint(__ldg(&cysigns[e])) & 0x80000000u;
            m |= m >> 16;
            uint2 u = g_AT2[(size_t)idx * B_UINT2 + tid];
            u.x ^= m;
            u.y ^= m;
            acc0 = __hadd2(acc0, *reinterpret_cast<__half2*>(&u.x));
            acc1 = __hadd2(acc1, *reinterpret_cast<__half2*>(&u.y));
        }
    }

    {   // final row flush
        const float2 f0 = __half22float2(acc0);
        const float2 f1 = __half22float2(acc1);
        sum += fabsf(f0.x) + fabsf(f0.y) + fabsf(f1.x) + fabsf(f1.y);
    }

    // Block reduction (2 warps)
    #pragma unroll
    for (int off = 16; off > 0; off >>= 1)
        sum += __shfl_down_sync(0xFFFFFFFFu, sum, off);
    const int lane = tid & 31, wid = tid >> 5;
    if (lane == 0) warp_sums[wid] = sum;
    __syncthreads();
    if (tid == 0) {
        const float w = warp_sums[0] + warp_sums[1];
        if (w != 0.0f) atomicAdd(&g_accum, (double)w);
        __threadfence();
        const unsigned ticket = atomicAdd(&g_done, 1u);
        if (ticket == (unsigned)(gridDim.x - 1)) {
            __threadfence();
            const double total = *((volatile double*)&g_accum);
            out[0] = (float)(total * (1.0 / ((double)N_CYC * (double)B_DIM)));
        }
    }
}

extern "C" void kernel_launch(void* const* d_in, const int* in_sizes, int n_in,
                              void* d_out, int out_size) {
    const float* c       = (const float*)d_in[0];
    const float* s       = (const float*)d_in[1];
    const float* cysigns = (const float*)d_in[2];
    const int*   cyinds  = (const int*)d_in[3];
    const int*   cyrows  = (const int*)d_in[4];
    float* out = (float*)d_out;
    const int E = in_sizes[4];

    dim3 t1(16, 16);
    dim3 g1((NB_DIM + 63) / 64, B_DIM / 64);
    phase1_atan2_transpose<<<g1, t1>>>(c, s);

    const int g2 = (E + P2_BASE - 1) / P2_BASE;
    phase2_cycle_sum<<<g2, P2_THREADS>>>(cysigns, cyinds, cyrows, out, E);
}